// round 3
// baseline (speedup 1.0000x reference)
#include <cuda_runtime.h>
#include <cuda_bf16.h>
#include <math.h>

// ---------------- problem constants ----------------
#define Bc   2
#define Sc   1024
#define Dc   2048
#define HQc  16
#define HKVc 4
#define HDc  128
#define Ec   32
#define TOPK 4
#define Fc   1024
#define FSc  2048
#define Tc   (Bc * Sc)          // 2048 tokens
#define REPc (HQc / HKVc)       // 4
#define EPSc 1e-6f

// ---------------- scratch (device globals; no allocations allowed) ----------------
__device__ float g_h[Tc * Dc];
__device__ float g_q[Tc * HQc * HDc];
__device__ float g_k[Tc * HKVc * HDc];
__device__ float g_v[Tc * HKVc * HDc];
__device__ float g_scores[(size_t)Bc * HQc * Sc * Sc];   // 134 MB
__device__ float g_attn[Tc * HQc * HDc];
__device__ float g_h2[Tc * Dc];
__device__ float g_x[Tc * Dc];
__device__ float g_g1[Tc * FSc];
__device__ float g_u1[Tc * FSc];
__device__ float g_sh[Tc * Dc];
__device__ float g_eg[Tc * TOPK * Fc];
__device__ float g_eu[Tc * TOPK * Fc];
__device__ int   g_topi[Tc * TOPK];
__device__ float g_topw[Tc * TOPK];
__device__ int   g_counts[Ec];
__device__ int   g_offsets[Ec];
__device__ int   g_cursor[Ec];
__device__ int   g_slot_tok[Tc * TOPK];
__device__ float g_slot_w[Tc * TOPK];

// ---------------- RMSNorm over D ----------------
__global__ void __launch_bounds__(256) rmsnorm_kernel(const float* __restrict__ in,
                                                      const float* __restrict__ g,
                                                      float* __restrict__ out) {
    int t = blockIdx.x;
    const float* xi = in + (size_t)t * Dc;
    float* xo = out + (size_t)t * Dc;
    float s = 0.f;
    for (int i = threadIdx.x; i < Dc; i += 256) { float v = xi[i]; s += v * v; }
    __shared__ float red[256];
    red[threadIdx.x] = s; __syncthreads();
    for (int st = 128; st > 0; st >>= 1) {
        if (threadIdx.x < st) red[threadIdx.x] += red[threadIdx.x + st];
        __syncthreads();
    }
    float inv = rsqrtf(red[0] / (float)Dc + EPSc);
    for (int i = threadIdx.x; i < Dc; i += 256) xo[i] = xi[i] * inv * g[i];
}

// ---------------- per-head RMSNorm + neox RoPE (in place) ----------------
__global__ void __launch_bounds__(128) qknorm_rope_kernel(float* __restrict__ buf,
                                                          const float* __restrict__ nrm,
                                                          const int* __restrict__ positions,
                                                          int H) {
    int t = blockIdx.x, h = blockIdx.y, d = threadIdx.x;
    float* p = buf + ((size_t)t * H + h) * HDc;
    float v = p[d];
    float ss = v * v;
    for (int o = 16; o > 0; o >>= 1) ss += __shfl_down_sync(0xffffffffu, ss, o);
    __shared__ float wred[4];
    if ((d & 31) == 0) wred[d >> 5] = ss;
    __syncthreads();
    float sum = wred[0] + wred[1] + wred[2] + wred[3];
    float inv = rsqrtf(sum / (float)HDc + EPSc);
    __shared__ float sv[HDc];
    sv[d] = v * inv * nrm[d];
    __syncthreads();
    float fpos = (float)positions[t];
    int i = (d < 64) ? d : d - 64;
    float freq = expf(-(float)i * (13.815510557964274f / 64.0f)); // ln(1e6)/64
    float ang = fpos * freq;
    float sn, cs; sincosf(ang, &sn, &cs);
    float x1 = (d < 64) ? sv[d] : sv[d - 64];
    float x2 = (d < 64) ? sv[d + 64] : sv[d];
    p[d] = (d < 64) ? (x1 * cs - x2 * sn) : (x1 * sn + x2 * cs);
}

// ---------- shared microkernel fragments (macro to keep the 4 GEMMs identical) ----------
#define GEMM_COMPUTE_TILE(AsBuf, BsBuf)                                        \
    _Pragma("unroll")                                                          \
    for (int kk = 0; kk < 16; kk++) {                                          \
        float4 a0 = *(const float4*)&AsBuf[kk][ty * 8];                        \
        float4 a1 = *(const float4*)&AsBuf[kk][ty * 8 + 4];                    \
        float4 b0 = *(const float4*)&BsBuf[kk][tx * 8];                        \
        float4 b1 = *(const float4*)&BsBuf[kk][tx * 8 + 4];                    \
        float ar[8] = {a0.x,a0.y,a0.z,a0.w,a1.x,a1.y,a1.z,a1.w};               \
        float br[8] = {b0.x,b0.y,b0.z,b0.w,b1.x,b1.y,b1.z,b1.w};               \
        _Pragma("unroll")                                                      \
        for (int i = 0; i < 8; i++)                                            \
            _Pragma("unroll")                                                  \
            for (int j = 0; j < 8; j++)                                        \
                acc[i][j] = fmaf(ar[i], br[j], acc[i][j]);                     \
    }

#define GEMM_STORE_SMEM(AsBuf, BsBuf)                                          \
    AsBuf[aCol + 0][aRow] = av0.x; AsBuf[aCol + 1][aRow] = av0.y;              \
    AsBuf[aCol + 2][aRow] = av0.z; AsBuf[aCol + 3][aRow] = av0.w;              \
    AsBuf[aCol + 4][aRow] = av1.x; AsBuf[aCol + 5][aRow] = av1.y;              \
    AsBuf[aCol + 6][aRow] = av1.z; AsBuf[aCol + 7][aRow] = av1.w;              \
    *(float4*)&BsBuf[bRow][bCol]     = bv0;                                    \
    *(float4*)&BsBuf[bRow][bCol + 4] = bv1;

// ---------------- 128x128x16 fp32 SGEMM, double-buffered: C = A@B (+addC) ----------------
__global__ void __launch_bounds__(256) sgemm_kernel(const float* __restrict__ A,
                                                    const float* __restrict__ B,
                                                    float* __restrict__ C,
                                                    const float* __restrict__ addC,
                                                    int M, int N, int K,
                                                    int lda, int ldb, int ldc) {
    __shared__ float As[2][16][128];
    __shared__ float Bs[2][16][128];
    int m0 = blockIdx.y * 128;
    int n0 = blockIdx.x * 128;
    int tid = threadIdx.x;
    int tx = tid & 15, ty = tid >> 4;
    float acc[8][8];
    #pragma unroll
    for (int i = 0; i < 8; i++)
        #pragma unroll
        for (int j = 0; j < 8; j++) acc[i][j] = 0.f;

    int aRow = tid >> 1, aCol = (tid & 1) * 8;
    int bRow = tid >> 4, bCol = (tid & 15) * 8;
    bool aValid = (m0 + aRow) < M;
    bool bValid = (n0 + bCol) < N;
    const float* Aptr = A + (size_t)(m0 + aRow) * lda + aCol;
    const float* Bptr = B + (size_t)bRow * ldb + n0 + bCol;

    const float4 z4 = make_float4(0.f, 0.f, 0.f, 0.f);
    float4 av0 = z4, av1 = z4, bv0 = z4, bv1 = z4;
    if (aValid) { av0 = *(const float4*)(Aptr);     av1 = *(const float4*)(Aptr + 4); }
    if (bValid) { bv0 = *(const float4*)(Bptr);     bv1 = *(const float4*)(Bptr + 4); }
    GEMM_STORE_SMEM(As[0], Bs[0]);
    __syncthreads();

    int nTiles = K >> 4;
    for (int t = 0; t < nTiles; t++) {
        int cur = t & 1, nxt = cur ^ 1;
        if (t + 1 < nTiles) {                 // issue next tile's loads first
            int k0 = (t + 1) << 4;
            av0 = z4; av1 = z4; bv0 = z4; bv1 = z4;
            if (aValid) {
                av0 = *(const float4*)(Aptr + k0);
                av1 = *(const float4*)(Aptr + k0 + 4);
            }
            if (bValid) {
                bv0 = *(const float4*)(Bptr + (size_t)k0 * ldb);
                bv1 = *(const float4*)(Bptr + (size_t)k0 * ldb + 4);
            }
        }
        if (cur == 0) { GEMM_COMPUTE_TILE(As[0], Bs[0]); }
        else          { GEMM_COMPUTE_TILE(As[1], Bs[1]); }
        if (t + 1 < nTiles) {
            if (nxt == 0) { GEMM_STORE_SMEM(As[0], Bs[0]); }
            else          { GEMM_STORE_SMEM(As[1], Bs[1]); }
        }
        __syncthreads();
    }
    #pragma unroll
    for (int i = 0; i < 8; i++) {
        int m = m0 + ty * 8 + i;
        if (m >= M) break;
        #pragma unroll
        for (int j = 0; j < 8; j++) {
            int n = n0 + tx * 8 + j;
            if (n < N) {
                float v = acc[i][j];
                if (addC) v += addC[(size_t)m * ldc + n];
                C[(size_t)m * ldc + n] = v;
            }
        }
    }
}

// ---------------- attention scores: per (b,h) 64x64 tiles, causal tile skip ----------------
__global__ void __launch_bounds__(256) qk_score_kernel(const float* __restrict__ q,
                                                       const float* __restrict__ k,
                                                       float* __restrict__ scores) {
    int k0 = blockIdx.x * 64, q0 = blockIdx.y * 64, z = blockIdx.z;
    if (k0 > q0 + 63) return;
    int b = z / HQc, h = z % HQc, kvh = h / REPc;
    __shared__ float Qs[16][64];
    __shared__ float Ks[16][64];
    int tid = threadIdx.x;
    int tx = tid & 15, ty = tid >> 4;
    float acc[4][4];
    #pragma unroll
    for (int i = 0; i < 4; i++)
        #pragma unroll
        for (int j = 0; j < 4; j++) acc[i][j] = 0.f;

    int lRow = tid >> 2, lCol = (tid & 3) * 4;
    const float* qb = q + ((size_t)(b * Sc + q0 + lRow) * HQc + h) * HDc + lCol;
    const float* kb = k + ((size_t)(b * Sc + k0 + lRow) * HKVc + kvh) * HDc + lCol;

    for (int c0 = 0; c0 < HDc; c0 += 16) {
        float4 qa = *(const float4*)(qb + c0);
        float4 ka = *(const float4*)(kb + c0);
        Qs[lCol + 0][lRow] = qa.x; Qs[lCol + 1][lRow] = qa.y;
        Qs[lCol + 2][lRow] = qa.z; Qs[lCol + 3][lRow] = qa.w;
        Ks[lCol + 0][lRow] = ka.x; Ks[lCol + 1][lRow] = ka.y;
        Ks[lCol + 2][lRow] = ka.z; Ks[lCol + 3][lRow] = ka.w;
        __syncthreads();
        #pragma unroll
        for (int kk = 0; kk < 16; kk++) {
            float qr[4], kr[4];
            #pragma unroll
            for (int i = 0; i < 4; i++) qr[i] = Qs[kk][ty * 4 + i];
            #pragma unroll
            for (int j = 0; j < 4; j++) kr[j] = Ks[kk][tx * 4 + j];
            #pragma unroll
            for (int i = 0; i < 4; i++)
                #pragma unroll
                for (int j = 0; j < 4; j++)
                    acc[i][j] = fmaf(qr[i], kr[j], acc[i][j]);
        }
        __syncthreads();
    }
    const float scale = 0.08838834764831845f; // 128^-0.5
    #pragma unroll
    for (int i = 0; i < 4; i++)
        #pragma unroll
        for (int j = 0; j < 4; j++)
            scores[((size_t)z * Sc + q0 + ty * 4 + i) * Sc + (k0 + tx * 4 + j)] =
                acc[i][j] * scale;
}

// ---------------- causal softmax: normalize [0..qi], zero-fill only the band attnv reads ----------------
__global__ void __launch_bounds__(256) softmax_kernel(float* __restrict__ scores) {
    int qi = blockIdx.x, z = blockIdx.y;
    float* row = scores + ((size_t)z * Sc + qi) * Sc;
    int n = qi + 1;
    int tid = threadIdx.x;
    __shared__ float red[256];
    float m = -1e30f;
    for (int i = tid; i < n; i += 256) m = fmaxf(m, row[i]);
    red[tid] = m; __syncthreads();
    for (int st = 128; st > 0; st >>= 1) {
        if (tid < st) red[tid] = fmaxf(red[tid], red[tid + st]);
        __syncthreads();
    }
    float mx = red[0]; __syncthreads();
    float s = 0.f;
    for (int i = tid; i < n; i += 256) s += expf(row[i] - mx);
    red[tid] = s; __syncthreads();
    for (int st = 128; st > 0; st >>= 1) {
        if (tid < st) red[tid] += red[tid + st];
        __syncthreads();
    }
    float inv = 1.f / red[0];
    for (int i = tid; i < n; i += 256) row[i] = expf(row[i] - mx) * inv;
    int bandEnd = (qi & ~127) + 128;   // attnv reads k in [0, bandEnd)
    for (int i = n + tid; i < bandEnd; i += 256) row[i] = 0.f;
}

// ---------------- attn = P @ V (double-buffered, causal K truncation) ----------------
__global__ void __launch_bounds__(256) attnv_kernel(const float* __restrict__ P,
                                                    const float* __restrict__ v,
                                                    float* __restrict__ attn) {
    int z = blockIdx.z;
    int b = z / HQc, h = z % HQc, kvh = h / REPc;
    int m0 = blockIdx.y * 128;
    const float* A = P + (size_t)z * Sc * Sc;                       // lda = Sc
    const float* Bb = v + ((size_t)b * Sc * HKVc + kvh) * HDc;      // ldb = HKVc*HDc
    const int ldb = HKVc * HDc;

    __shared__ float As[2][16][128];
    __shared__ float Bs[2][16][128];
    int tid = threadIdx.x;
    int tx = tid & 15, ty = tid >> 4;
    float acc[8][8];
    #pragma unroll
    for (int i = 0; i < 8; i++)
        #pragma unroll
        for (int j = 0; j < 8; j++) acc[i][j] = 0.f;

    int aRow = tid >> 1, aCol = (tid & 1) * 8;
    int bRow = tid >> 4, bCol = (tid & 15) * 8;
    const float* Aptr = A + (size_t)(m0 + aRow) * Sc + aCol;
    const float* Bptr = Bb + (size_t)bRow * ldb + bCol;

    float4 av0 = *(const float4*)(Aptr);
    float4 av1 = *(const float4*)(Aptr + 4);
    float4 bv0 = *(const float4*)(Bptr);
    float4 bv1 = *(const float4*)(Bptr + 4);
    GEMM_STORE_SMEM(As[0], Bs[0]);
    __syncthreads();

    int nTiles = (m0 + 128) >> 4;   // rows beyond qi within the band hold zeroed probs
    for (int t = 0; t < nTiles; t++) {
        int cur = t & 1, nxt = cur ^ 1;
        if (t + 1 < nTiles) {
            int k0 = (t + 1) << 4;
            av0 = *(const float4*)(Aptr + k0);
            av1 = *(const float4*)(Aptr + k0 + 4);
            bv0 = *(const float4*)(Bptr + (size_t)k0 * ldb);
            bv1 = *(const float4*)(Bptr + (size_t)k0 * ldb + 4);
        }
        if (cur == 0) { GEMM_COMPUTE_TILE(As[0], Bs[0]); }
        else          { GEMM_COMPUTE_TILE(As[1], Bs[1]); }
        if (t + 1 < nTiles) {
            if (nxt == 0) { GEMM_STORE_SMEM(As[0], Bs[0]); }
            else          { GEMM_STORE_SMEM(As[1], Bs[1]); }
        }
        __syncthreads();
    }
    #pragma unroll
    for (int i = 0; i < 8; i++) {
        int m = m0 + ty * 8 + i;
        #pragma unroll
        for (int j = 0; j < 8; j++) {
            int n = tx * 8 + j;
            attn[((size_t)(b * Sc + m) * HQc + h) * HDc + n] = acc[i][j];
        }
    }
}

// ---------------- elementwise silu(a)*b -> a ----------------
__global__ void __launch_bounds__(256) silumul_kernel(float* __restrict__ a,
                                                      const float* __restrict__ b,
                                                      int n) {
    int i = blockIdx.x * 256 + threadIdx.x;
    if (i < n) {
        float v = a[i];
        a[i] = v / (1.f + expf(-v)) * b[i];
    }
}

// ---------------- router: logits, sigmoid, top-4, renorm ----------------
__global__ void __launch_bounds__(256) router_kernel(const float* __restrict__ x,
                                                     const float* __restrict__ gate_w) {
    int t = blockIdx.x;
    int tid = threadIdx.x;
    int lane = tid & 31, w = tid >> 5;   // 8 warps x 4 experts each
    const float* xr = x + (size_t)t * Dc;
    float acc[4] = {0.f, 0.f, 0.f, 0.f};
    for (int d = lane; d < Dc; d += 32) {
        float xv = xr[d];
        #pragma unroll
        for (int j = 0; j < 4; j++)
            acc[j] = fmaf(xv, gate_w[(size_t)d * Ec + w * 4 + j], acc[j]);
    }
    #pragma unroll
    for (int j = 0; j < 4; j++)
        for (int o = 16; o > 0; o >>= 1)
            acc[j] += __shfl_down_sync(0xffffffffu, acc[j], o);
    __shared__ float lg[Ec];
    if (lane == 0) {
        #pragma unroll
        for (int j = 0; j < 4; j++) lg[w * 4 + j] = acc[j];
    }
    __syncthreads();
    if (tid == 0) {
        float gg[Ec];
        #pragma unroll
        for (int e = 0; e < Ec; e++) gg[e] = 1.f / (1.f + expf(-lg[e]));
        float tv[TOPK]; int ti[TOPK]; float sum = 0.f;
        for (int j = 0; j < TOPK; j++) {
            int best = 0; float bv = -1e30f;
            for (int e = 0; e < Ec; e++)
                if (gg[e] > bv) { bv = gg[e]; best = e; }
            gg[best] = -1e30f;
            tv[j] = bv; ti[j] = best; sum += bv;
        }
        float inv = 1.f / sum;
        for (int j = 0; j < TOPK; j++) {
            g_topi[t * TOPK + j] = ti[j];
            g_topw[t * TOPK + j] = tv[j] * inv;
        }
    }
}

// ---------------- expert grouping ----------------
__global__ void __launch_bounds__(256) count_scan_kernel() {
    __shared__ int sc[Ec];
    int tid = threadIdx.x;
    if (tid < Ec) sc[tid] = 0;
    __syncthreads();
    for (int i = tid; i < Tc * TOPK; i += 256) atomicAdd(&sc[g_topi[i]], 1);
    __syncthreads();
    if (tid == 0) {
        int run = 0;
        for (int e = 0; e < Ec; e++) {
            g_offsets[e] = run; g_cursor[e] = run; g_counts[e] = sc[e];
            run += sc[e];
        }
    }
}

__global__ void __launch_bounds__(256) scatter_kernel() {
    int i = blockIdx.x * 256 + threadIdx.x;
    if (i < Tc * TOPK) {
        int t = i >> 2;
        int e = g_topi[i];
        int p = atomicAdd(&g_cursor[e], 1);
        g_slot_tok[p] = t;
        g_slot_w[p] = g_topw[i];
    }
}

// ---------------- routed expert up/gate GEMM (gathered A rows, double-buffered) ----------------
__global__ void __launch_bounds__(256) moe_up_kernel(const float* __restrict__ X,
                                                     const float* __restrict__ W,
                                                     float* __restrict__ Cb,
                                                     int N, int Kd) {
    int e = blockIdx.z;
    int cnt = g_counts[e];
    int m0 = blockIdx.y * 128;
    if (m0 >= cnt) return;
    int off = g_offsets[e];
    int n0 = blockIdx.x * 128;

    __shared__ float As[2][16][128];
    __shared__ float Bs[2][16][128];
    int tid = threadIdx.x;
    int tx = tid & 15, ty = tid >> 4;
    float acc[8][8];
    #pragma unroll
    for (int i = 0; i < 8; i++)
        #pragma unroll
        for (int j = 0; j < 8; j++) acc[i][j] = 0.f;

    int aRow = tid >> 1, aCol = (tid & 1) * 8;
    int bRow = tid >> 4, bCol = (tid & 15) * 8;
    bool aValid = (m0 + aRow) < cnt;
    const float* Aptr = X;
    if (aValid) Aptr = X + (size_t)g_slot_tok[off + m0 + aRow] * Kd + aCol;
    const float* Bptr = W + (size_t)e * Kd * N + (size_t)bRow * N + n0 + bCol;

    const float4 z4 = make_float4(0.f, 0.f, 0.f, 0.f);
    float4 av0 = z4, av1 = z4;
    if (aValid) { av0 = *(const float4*)(Aptr); av1 = *(const float4*)(Aptr + 4); }
    float4 bv0 = *(const float4*)(Bptr);
    float4 bv1 = *(const float4*)(Bptr + 4);
    GEMM_STORE_SMEM(As[0], Bs[0]);
    __syncthreads();

    int nTiles = Kd >> 4;
    for (int t = 0; t < nTiles; t++) {
        int cur = t & 1, nxt = cur ^ 1;
        if (t + 1 < nTiles) {
            int k0 = (t + 1) << 4;
            av0 = z4; av1 = z4;
            if (aValid) {
                av0 = *(const float4*)(Aptr + k0);
                av1 = *(const float4*)(Aptr + k0 + 4);
            }
            bv0 = *(const float4*)(Bptr + (size_t)k0 * N);
            bv1 = *(const float4*)(Bptr + (size_t)k0 * N + 4);
        }
        if (cur == 0) { GEMM_COMPUTE_TILE(As[0], Bs[0]); }
        else          { GEMM_COMPUTE_TILE(As[1], Bs[1]); }
        if (t + 1 < nTiles) {
            if (nxt == 0) { GEMM_STORE_SMEM(As[0], Bs[0]); }
            else          { GEMM_STORE_SMEM(As[1], Bs[1]); }
        }
        __syncthreads();
    }
    #pragma unroll
    for (int i = 0; i < 8; i++) {
        int r = m0 + ty * 8 + i;
        if (r >= cnt) break;
        #pragma unroll
        for (int j = 0; j < 8; j++)
            Cb[(size_t)(off + r) * N + n0 + tx * 8 + j] = acc[i][j];
    }
}

// ---------------- routed expert down GEMM (double-buffered): atomicAdd w*(inter @ wd) ----------------
__global__ void __launch_bounds__(256) moe_down_kernel(const float* __restrict__ Ibuf,
                                                       const float* __restrict__ Wd,
                                                       float* __restrict__ out,
                                                       int N, int Kd) {
    int e = blockIdx.z;
    int cnt = g_counts[e];
    int m0 = blockIdx.y * 128;
    if (m0 >= cnt) return;
    int off = g_offsets[e];
    int n0 = blockIdx.x * 128;

    __shared__ float As[2][16][128];
    __shared__ float Bs[2][16][128];
    int tid = threadIdx.x;
    int tx = tid & 15, ty = tid >> 4;
    float acc[8][8];
    #pragma unroll
    for (int i = 0; i < 8; i++)
        #pragma unroll
        for (int j = 0; j < 8; j++) acc[i][j] = 0.f;

    int aRow = tid >> 1, aCol = (tid & 1) * 8;
    int bRow = tid >> 4, bCol = (tid & 15) * 8;
    bool aValid = (m0 + aRow) < cnt;
    const float* Aptr = Ibuf + (size_t)(off + m0 + aRow) * Kd + aCol;
    const float* Bptr = Wd + (size_t)e * Kd * N + (size_t)bRow * N + n0 + bCol;

    const float4 z4 = make_float4(0.f, 0.f, 0.f, 0.f);
    float4 av0 = z4, av1 = z4;
    if (aValid) { av0 = *(const float4*)(Aptr); av1 = *(const float4*)(Aptr + 4); }
    float4 bv0 = *(const float4*)(Bptr);
    float4 bv1 = *(const float4*)(Bptr + 4);
    GEMM_STORE_SMEM(As[0], Bs[0]);
    __syncthreads();

    int nTiles = Kd >> 4;
    for (int t = 0; t < nTiles; t++) {
        int cur = t & 1, nxt = cur ^ 1;
        if (t + 1 < nTiles) {
            int k0 = (t + 1) << 4;
            av0 = z4; av1 = z4;
            if (aValid) {
                av0 = *(const float4*)(Aptr + k0);
                av1 = *(const float4*)(Aptr + k0 + 4);
            }
            bv0 = *(const float4*)(Bptr + (size_t)k0 * N);
            bv1 = *(const float4*)(Bptr + (size_t)k0 * N + 4);
        }
        if (cur == 0) { GEMM_COMPUTE_TILE(As[0], Bs[0]); }
        else          { GEMM_COMPUTE_TILE(As[1], Bs[1]); }
        if (t + 1 < nTiles) {
            if (nxt == 0) { GEMM_STORE_SMEM(As[0], Bs[0]); }
            else          { GEMM_STORE_SMEM(As[1], Bs[1]); }
        }
        __syncthreads();
    }
    #pragma unroll
    for (int i = 0; i < 8; i++) {
        int r = m0 + ty * 8 + i;
        if (r >= cnt) break;
        int slot = off + r;
        int tok = g_slot_tok[slot];
        float wgt = g_slot_w[slot];
        #pragma unroll
        for (int j = 0; j < 8; j++)
            atomicAdd(&out[(size_t)tok * N + n0 + tx * 8 + j], wgt * acc[i][j]);
    }
}

// ---------------- combine: out = shared + resid2 (moe atomicAdded afterwards) ----------------
__global__ void __launch_bounds__(256) combine_kernel(float* __restrict__ out) {
    int i = blockIdx.x * 256 + threadIdx.x;
    if (i < Tc * Dc) out[i] = g_sh[i] + g_h2[i];
}

// ---------------- host launch ----------------
extern "C" void kernel_launch(void* const* d_in, const int* in_sizes, int n_in,
                              void* d_out, int out_size) {
    const int*   positions = (const int*)d_in[0];
    const float* hidden    = (const float*)d_in[1];
    const float* in_ln     = (const float*)d_in[2];
    const float* post_ln   = (const float*)d_in[3];
    const float* q_norm    = (const float*)d_in[4];
    const float* k_norm    = (const float*)d_in[5];
    const float* wq        = (const float*)d_in[6];
    const float* wk        = (const float*)d_in[7];
    const float* wv        = (const float*)d_in[8];
    const float* wo        = (const float*)d_in[9];
    const float* gate_w    = (const float*)d_in[10];
    const float* sh_wg     = (const float*)d_in[11];
    const float* sh_wu     = (const float*)d_in[12];
    const float* sh_wd     = (const float*)d_in[13];
    const float* e_wg      = (const float*)d_in[14];
    const float* e_wu      = (const float*)d_in[15];
    const float* e_wd      = (const float*)d_in[16];
    float* out = (float*)d_out;

    float *p_h, *p_q, *p_k, *p_v, *p_scores, *p_attn, *p_h2, *p_x, *p_g1, *p_u1,
          *p_sh, *p_eg, *p_eu;
    cudaGetSymbolAddress((void**)&p_h, g_h);
    cudaGetSymbolAddress((void**)&p_q, g_q);
    cudaGetSymbolAddress((void**)&p_k, g_k);
    cudaGetSymbolAddress((void**)&p_v, g_v);
    cudaGetSymbolAddress((void**)&p_scores, g_scores);
    cudaGetSymbolAddress((void**)&p_attn, g_attn);
    cudaGetSymbolAddress((void**)&p_h2, g_h2);
    cudaGetSymbolAddress((void**)&p_x, g_x);
    cudaGetSymbolAddress((void**)&p_g1, g_g1);
    cudaGetSymbolAddress((void**)&p_u1, g_u1);
    cudaGetSymbolAddress((void**)&p_sh, g_sh);
    cudaGetSymbolAddress((void**)&p_eg, g_eg);
    cudaGetSymbolAddress((void**)&p_eu, g_eu);

    // 1. input RMSNorm
    rmsnorm_kernel<<<Tc, 256>>>(hidden, in_ln, p_h);

    // 2-4. QKV projections
    sgemm_kernel<<<dim3((HQc*HDc)/128, Tc/128), 256>>>(p_h, wq, p_q, nullptr,
        Tc, HQc*HDc, Dc, Dc, HQc*HDc, HQc*HDc);
    sgemm_kernel<<<dim3((HKVc*HDc)/128, Tc/128), 256>>>(p_h, wk, p_k, nullptr,
        Tc, HKVc*HDc, Dc, Dc, HKVc*HDc, HKVc*HDc);
    sgemm_kernel<<<dim3((HKVc*HDc)/128, Tc/128), 256>>>(p_h, wv, p_v, nullptr,
        Tc, HKVc*HDc, Dc, Dc, HKVc*HDc, HKVc*HDc);

    // 5. qk-norm + RoPE
    qknorm_rope_kernel<<<dim3(Tc, HQc), 128>>>(p_q, q_norm, positions, HQc);
    qknorm_rope_kernel<<<dim3(Tc, HKVc), 128>>>(p_k, k_norm, positions, HKVc);

    // 6. scores (causal tile skip)
    qk_score_kernel<<<dim3(Sc/64, Sc/64, Bc*HQc), 256>>>(p_q, p_k, p_scores);

    // 7. causal softmax (bounded zero-fill)
    softmax_kernel<<<dim3(Sc, Bc*HQc), 256>>>(p_scores);

    // 8. attn = P @ V
    attnv_kernel<<<dim3(1, Sc/128, Bc*HQc), 256>>>(p_scores, p_v, p_attn);

    // 9. output proj + residual
    sgemm_kernel<<<dim3(Dc/128, Tc/128), 256>>>(p_attn, wo, p_h2, hidden,
        Tc, Dc, HQc*HDc, HQc*HDc, Dc, Dc);

    // 10. post-attn RMSNorm
    rmsnorm_kernel<<<Tc, 256>>>(p_h2, post_ln, p_x);

    // 11-13. shared expert SwiGLU
    sgemm_kernel<<<dim3(FSc/128, Tc/128), 256>>>(p_x, sh_wg, p_g1, nullptr,
        Tc, FSc, Dc, Dc, FSc, FSc);
    sgemm_kernel<<<dim3(FSc/128, Tc/128), 256>>>(p_x, sh_wu, p_u1, nullptr,
        Tc, FSc, Dc, Dc, FSc, FSc);
    silumul_kernel<<<(Tc*FSc + 255)/256, 256>>>(p_g1, p_u1, Tc*FSc);
    sgemm_kernel<<<dim3(Dc/128, Tc/128), 256>>>(p_g1, sh_wd, p_sh, nullptr,
        Tc, Dc, FSc, FSc, Dc, Dc);

    // 14-16. routing + grouping
    router_kernel<<<Tc, 256>>>(p_x, gate_w);
    count_scan_kernel<<<1, 256>>>();
    scatter_kernel<<<(Tc*TOPK + 255)/256, 256>>>();

    // 17-18. routed experts: gate/up (gathered), silu-mul
    moe_up_kernel<<<dim3(Fc/128, (Tc*TOPK)/128, Ec), 256>>>(p_x, e_wg, p_eg, Fc, Dc);
    moe_up_kernel<<<dim3(Fc/128, (Tc*TOPK)/128, Ec), 256>>>(p_x, e_wu, p_eu, Fc, Dc);
    silumul_kernel<<<(Tc*TOPK*Fc + 255)/256, 256>>>(p_eg, p_eu, Tc*TOPK*Fc);

    // 19. init out = shared + resid2 (must precede down-proj atomics)
    combine_kernel<<<(Tc*Dc + 255)/256, 256>>>(out);

    // 20. routed down-proj, weighted atomic accumulate into out
    moe_down_kernel<<<dim3(Dc/128, (Tc*TOPK)/128, Ec), 256>>>(p_eg, e_wd, out, Dc, Fc);
}

// round 4
// speedup vs baseline: 2.1136x; 2.1136x over previous
#include <cuda_runtime.h>
#include <cuda_bf16.h>
#include <math.h>
#include <stdint.h>

// ---------------- problem constants ----------------
#define Bc   2
#define Sc   1024
#define Dc   2048
#define HQc  16
#define HKVc 4
#define HDc  128
#define Ec   32
#define TOPK 4
#define Fc   1024
#define FSc  2048
#define Tc   (Bc * Sc)          // 2048 tokens
#define REPc (HQc / HKVc)       // 4
#define EPSc 1e-6f

// ---------------- scratch (device globals; no allocations allowed) ----------------
__device__ float g_h[Tc * Dc];
__device__ float g_q[Tc * HQc * HDc];
__device__ float g_k[Tc * HKVc * HDc];
__device__ float g_v[Tc * HKVc * HDc];
__device__ float g_scores[(size_t)Bc * HQc * Sc * Sc];   // 134 MB
__device__ float g_attn[Tc * HQc * HDc];
__device__ float g_h2[Tc * Dc];
__device__ float g_x[Tc * Dc];
__device__ float g_g1[Tc * FSc];
__device__ float g_u1[Tc * FSc];
__device__ float g_sh[Tc * Dc];
__device__ float g_eg[Tc * TOPK * Fc];
__device__ float g_eu[Tc * TOPK * Fc];
__device__ int   g_topi[Tc * TOPK];
__device__ float g_topw[Tc * TOPK];
__device__ int   g_counts[Ec];
__device__ int   g_offsets[Ec];
__device__ int   g_cursor[Ec];
__device__ int   g_slot_tok[Tc * TOPK];
__device__ float g_slot_w[Tc * TOPK];

// ---------------- tf32 helpers ----------------
__device__ __forceinline__ uint32_t f2tf(float x) {
    uint32_t r;
    asm("cvt.rna.tf32.f32 %0, %1;" : "=r"(r) : "f"(x));
    return r;
}
__device__ __forceinline__ void mma_tf32(float* c, const uint32_t* a, const uint32_t* b) {
    asm volatile(
        "mma.sync.aligned.m16n8k8.row.col.f32.tf32.tf32.f32 "
        "{%0,%1,%2,%3}, {%4,%5,%6,%7}, {%8,%9}, {%0,%1,%2,%3};"
        : "+f"(c[0]), "+f"(c[1]), "+f"(c[2]), "+f"(c[3])
        : "r"(a[0]), "r"(a[1]), "r"(a[2]), "r"(a[3]), "r"(b[0]), "r"(b[1]));
}

// ---------------- RMSNorm over D ----------------
__global__ void __launch_bounds__(256) rmsnorm_kernel(const float* __restrict__ in,
                                                      const float* __restrict__ g,
                                                      float* __restrict__ out) {
    int t = blockIdx.x;
    const float* xi = in + (size_t)t * Dc;
    float* xo = out + (size_t)t * Dc;
    float s = 0.f;
    for (int i = threadIdx.x; i < Dc; i += 256) { float v = xi[i]; s += v * v; }
    __shared__ float red[256];
    red[threadIdx.x] = s; __syncthreads();
    for (int st = 128; st > 0; st >>= 1) {
        if (threadIdx.x < st) red[threadIdx.x] += red[threadIdx.x + st];
        __syncthreads();
    }
    float inv = rsqrtf(red[0] / (float)Dc + EPSc);
    for (int i = threadIdx.x; i < Dc; i += 256) xo[i] = xi[i] * inv * g[i];
}

// ---------------- per-head RMSNorm + neox RoPE (in place) ----------------
__global__ void __launch_bounds__(128) qknorm_rope_kernel(float* __restrict__ buf,
                                                          const float* __restrict__ nrm,
                                                          const int* __restrict__ positions,
                                                          int H) {
    int t = blockIdx.x, h = blockIdx.y, d = threadIdx.x;
    float* p = buf + ((size_t)t * H + h) * HDc;
    float v = p[d];
    float ss = v * v;
    for (int o = 16; o > 0; o >>= 1) ss += __shfl_down_sync(0xffffffffu, ss, o);
    __shared__ float wred[4];
    if ((d & 31) == 0) wred[d >> 5] = ss;
    __syncthreads();
    float sum = wred[0] + wred[1] + wred[2] + wred[3];
    float inv = rsqrtf(sum / (float)HDc + EPSc);
    __shared__ float sv[HDc];
    sv[d] = v * inv * nrm[d];
    __syncthreads();
    float fpos = (float)positions[t];
    int i = (d < 64) ? d : d - 64;
    float freq = expf(-(float)i * (13.815510557964274f / 64.0f)); // ln(1e6)/64
    float ang = fpos * freq;
    float sn, cs; sincosf(ang, &sn, &cs);
    float x1 = (d < 64) ? sv[d] : sv[d - 64];
    float x2 = (d < 64) ? sv[d + 64] : sv[d];
    p[d] = (d < 64) ? (x1 * cs - x2 * sn) : (x1 * sn + x2 * cs);
}

// ---------- tf32 GEMM shared fragments ----------
// Block 128x128, K-tile 16, 8 warps (4x2). Warp tile 32x64 via m16n8k8 mma.
// As stride 20: frag-read banks (20*grp+tig)%32 all distinct.
// Bs stride 136: frag-read banks (8*tig+grp)%32 all distinct.

#define TF_DECL                                                                 \
    int tid = threadIdx.x;                                                      \
    int lane = tid & 31, warp = tid >> 5;                                       \
    int grp = lane >> 2, tig = lane & 3;                                        \
    int wm = warp >> 1, wn = warp & 1;                                          \
    float acc[2][8][4];                                                         \
    _Pragma("unroll")                                                           \
    for (int i_ = 0; i_ < 2; i_++)                                              \
        _Pragma("unroll")                                                       \
        for (int j_ = 0; j_ < 8; j_++)                                          \
            _Pragma("unroll")                                                   \
            for (int q_ = 0; q_ < 4; q_++) acc[i_][j_][q_] = 0.f;               \
    int aRow = tid >> 1, aCol = (tid & 1) * 8;                                  \
    int bRow = tid >> 4, bCol = (tid & 15) * 8;

#define TF_STORE(buf) {                                                         \
    uint32_t* ap_ = &As[buf][aRow][aCol];                                       \
    ap_[0] = f2tf(av0.x); ap_[1] = f2tf(av0.y);                                 \
    ap_[2] = f2tf(av0.z); ap_[3] = f2tf(av0.w);                                 \
    ap_[4] = f2tf(av1.x); ap_[5] = f2tf(av1.y);                                 \
    ap_[6] = f2tf(av1.z); ap_[7] = f2tf(av1.w);                                 \
    uint32_t* bp_ = &Bs[buf][bRow][bCol];                                       \
    bp_[0] = f2tf(bv0.x); bp_[1] = f2tf(bv0.y);                                 \
    bp_[2] = f2tf(bv0.z); bp_[3] = f2tf(bv0.w);                                 \
    bp_[4] = f2tf(bv1.x); bp_[5] = f2tf(bv1.y);                                 \
    bp_[6] = f2tf(bv1.z); bp_[7] = f2tf(bv1.w); }

#define TF_COMPUTE(buf)                                                         \
    _Pragma("unroll")                                                           \
    for (int ks_ = 0; ks_ < 2; ks_++) {                                         \
        int kb_ = ks_ * 8;                                                      \
        uint32_t af_[2][4];                                                     \
        _Pragma("unroll")                                                       \
        for (int mti_ = 0; mti_ < 2; mti_++) {                                  \
            int r0_ = wm * 32 + mti_ * 16 + grp;                                \
            af_[mti_][0] = As[buf][r0_][kb_ + tig];                             \
            af_[mti_][1] = As[buf][r0_ + 8][kb_ + tig];                         \
            af_[mti_][2] = As[buf][r0_][kb_ + tig + 4];                         \
            af_[mti_][3] = As[buf][r0_ + 8][kb_ + tig + 4];                     \
        }                                                                       \
        _Pragma("unroll")                                                       \
        for (int nti_ = 0; nti_ < 8; nti_++) {                                  \
            uint32_t bf_[2];                                                    \
            int nn_ = wn * 64 + nti_ * 8 + grp;                                 \
            bf_[0] = Bs[buf][kb_ + tig][nn_];                                   \
            bf_[1] = Bs[buf][kb_ + tig + 4][nn_];                               \
            mma_tf32(acc[0][nti_], af_[0], bf_);                                \
            mma_tf32(acc[1][nti_], af_[1], bf_);                                \
        }                                                                       \
    }

// ---------------- tf32 SGEMM: C[M,N] = A[M,K]@B[K,N] (+addC); M,N mult of 128, K mult of 16 ----------------
__global__ void __launch_bounds__(256) sgemm_tf32_kernel(const float* __restrict__ A,
                                                         const float* __restrict__ B,
                                                         float* __restrict__ C,
                                                         const float* __restrict__ addC,
                                                         int M, int N, int K,
                                                         int lda, int ldb, int ldc) {
    __shared__ uint32_t As[2][128][20];
    __shared__ uint32_t Bs[2][16][136];
    int m0 = blockIdx.y * 128;
    int n0 = blockIdx.x * 128;
    TF_DECL;
    const float* Aptr = A + (size_t)(m0 + aRow) * lda + aCol;
    const float* Bptr = B + (size_t)bRow * ldb + n0 + bCol;

    float4 av0 = *(const float4*)(Aptr);
    float4 av1 = *(const float4*)(Aptr + 4);
    float4 bv0 = *(const float4*)(Bptr);
    float4 bv1 = *(const float4*)(Bptr + 4);
    TF_STORE(0);
    __syncthreads();

    int nTiles = K >> 4;
    for (int t = 0; t < nTiles; t++) {
        int cur = t & 1, nxt = cur ^ 1;
        if (t + 1 < nTiles) {
            int k0 = (t + 1) << 4;
            av0 = *(const float4*)(Aptr + k0);
            av1 = *(const float4*)(Aptr + k0 + 4);
            bv0 = *(const float4*)(Bptr + (size_t)k0 * ldb);
            bv1 = *(const float4*)(Bptr + (size_t)k0 * ldb + 4);
        }
        if (cur == 0) { TF_COMPUTE(0); } else { TF_COMPUTE(1); }
        if (t + 1 < nTiles) {
            if (nxt == 0) { TF_STORE(0); } else { TF_STORE(1); }
        }
        __syncthreads();
    }
    #pragma unroll
    for (int mti = 0; mti < 2; mti++)
        #pragma unroll
        for (int nti = 0; nti < 8; nti++) {
            int m = m0 + wm * 32 + mti * 16 + grp;
            int n = n0 + wn * 64 + nti * 8 + tig * 2;
            const float* cc = acc[mti][nti];
            float v0 = cc[0], v1 = cc[1], v2 = cc[2], v3 = cc[3];
            if (addC) {
                v0 += addC[(size_t)m * ldc + n];
                v1 += addC[(size_t)m * ldc + n + 1];
                v2 += addC[(size_t)(m + 8) * ldc + n];
                v3 += addC[(size_t)(m + 8) * ldc + n + 1];
            }
            C[(size_t)m * ldc + n]           = v0;
            C[(size_t)m * ldc + n + 1]       = v1;
            C[(size_t)(m + 8) * ldc + n]     = v2;
            C[(size_t)(m + 8) * ldc + n + 1] = v3;
        }
}

// ---------------- attention scores (fp32 FMA; accuracy-critical, small flops) ----------------
__global__ void __launch_bounds__(256) qk_score_kernel(const float* __restrict__ q,
                                                       const float* __restrict__ k,
                                                       float* __restrict__ scores) {
    int k0 = blockIdx.x * 64, q0 = blockIdx.y * 64, z = blockIdx.z;
    if (k0 > q0 + 63) return;
    int b = z / HQc, h = z % HQc, kvh = h / REPc;
    __shared__ float Qs[16][64];
    __shared__ float Ks[16][64];
    int tid = threadIdx.x;
    int tx = tid & 15, ty = tid >> 4;
    float acc[4][4];
    #pragma unroll
    for (int i = 0; i < 4; i++)
        #pragma unroll
        for (int j = 0; j < 4; j++) acc[i][j] = 0.f;

    int lRow = tid >> 2, lCol = (tid & 3) * 4;
    const float* qb = q + ((size_t)(b * Sc + q0 + lRow) * HQc + h) * HDc + lCol;
    const float* kb = k + ((size_t)(b * Sc + k0 + lRow) * HKVc + kvh) * HDc + lCol;

    for (int c0 = 0; c0 < HDc; c0 += 16) {
        float4 qa = *(const float4*)(qb + c0);
        float4 ka = *(const float4*)(kb + c0);
        Qs[lCol + 0][lRow] = qa.x; Qs[lCol + 1][lRow] = qa.y;
        Qs[lCol + 2][lRow] = qa.z; Qs[lCol + 3][lRow] = qa.w;
        Ks[lCol + 0][lRow] = ka.x; Ks[lCol + 1][lRow] = ka.y;
        Ks[lCol + 2][lRow] = ka.z; Ks[lCol + 3][lRow] = ka.w;
        __syncthreads();
        #pragma unroll
        for (int kk = 0; kk < 16; kk++) {
            float qr[4], kr[4];
            #pragma unroll
            for (int i = 0; i < 4; i++) qr[i] = Qs[kk][ty * 4 + i];
            #pragma unroll
            for (int j = 0; j < 4; j++) kr[j] = Ks[kk][tx * 4 + j];
            #pragma unroll
            for (int i = 0; i < 4; i++)
                #pragma unroll
                for (int j = 0; j < 4; j++)
                    acc[i][j] = fmaf(qr[i], kr[j], acc[i][j]);
        }
        __syncthreads();
    }
    const float scale = 0.08838834764831845f; // 128^-0.5
    #pragma unroll
    for (int i = 0; i < 4; i++)
        #pragma unroll
        for (int j = 0; j < 4; j++)
            scores[((size_t)z * Sc + q0 + ty * 4 + i) * Sc + (k0 + tx * 4 + j)] =
                acc[i][j] * scale;
}

// ---------------- causal softmax: normalize [0..qi], zero-fill only the band attnv reads ----------------
__global__ void __launch_bounds__(256) softmax_kernel(float* __restrict__ scores) {
    int qi = blockIdx.x, z = blockIdx.y;
    float* row = scores + ((size_t)z * Sc + qi) * Sc;
    int n = qi + 1;
    int tid = threadIdx.x;
    __shared__ float red[256];
    float m = -1e30f;
    for (int i = tid; i < n; i += 256) m = fmaxf(m, row[i]);
    red[tid] = m; __syncthreads();
    for (int st = 128; st > 0; st >>= 1) {
        if (tid < st) red[tid] = fmaxf(red[tid], red[tid + st]);
        __syncthreads();
    }
    float mx = red[0]; __syncthreads();
    float s = 0.f;
    for (int i = tid; i < n; i += 256) s += expf(row[i] - mx);
    red[tid] = s; __syncthreads();
    for (int st = 128; st > 0; st >>= 1) {
        if (tid < st) red[tid] += red[tid + st];
        __syncthreads();
    }
    float inv = 1.f / red[0];
    for (int i = tid; i < n; i += 256) row[i] = expf(row[i] - mx) * inv;
    int bandEnd = (qi & ~127) + 128;   // attnv reads k in [0, bandEnd)
    for (int i = n + tid; i < bandEnd; i += 256) row[i] = 0.f;
}

// ---------------- attn = P @ V (tf32, causal K truncation) ----------------
__global__ void __launch_bounds__(256) attnv_tf32_kernel(const float* __restrict__ P,
                                                         const float* __restrict__ v,
                                                         float* __restrict__ attn) {
    __shared__ uint32_t As[2][128][20];
    __shared__ uint32_t Bs[2][16][136];
    int z = blockIdx.z;
    int b = z / HQc, h = z % HQc, kvh = h / REPc;
    int m0 = blockIdx.y * 128;
    const float* A = P + (size_t)z * Sc * Sc;                   // lda = Sc
    const float* Bb = v + ((size_t)b * Sc * HKVc + kvh) * HDc;  // ldb = 512
    const int ldb = HKVc * HDc;
    TF_DECL;
    const float* Aptr = A + (size_t)(m0 + aRow) * Sc + aCol;
    const float* Bptr = Bb + (size_t)bRow * ldb + bCol;

    float4 av0 = *(const float4*)(Aptr);
    float4 av1 = *(const float4*)(Aptr + 4);
    float4 bv0 = *(const float4*)(Bptr);
    float4 bv1 = *(const float4*)(Bptr + 4);
    TF_STORE(0);
    __syncthreads();

    int nTiles = (m0 + 128) >> 4;   // rows beyond qi within the band hold zeroed probs
    for (int t = 0; t < nTiles; t++) {
        int cur = t & 1, nxt = cur ^ 1;
        if (t + 1 < nTiles) {
            int k0 = (t + 1) << 4;
            av0 = *(const float4*)(Aptr + k0);
            av1 = *(const float4*)(Aptr + k0 + 4);
            bv0 = *(const float4*)(Bptr + (size_t)k0 * ldb);
            bv1 = *(const float4*)(Bptr + (size_t)k0 * ldb + 4);
        }
        if (cur == 0) { TF_COMPUTE(0); } else { TF_COMPUTE(1); }
        if (t + 1 < nTiles) {
            if (nxt == 0) { TF_STORE(0); } else { TF_STORE(1); }
        }
        __syncthreads();
    }
    #pragma unroll
    for (int mti = 0; mti < 2; mti++)
        #pragma unroll
        for (int nti = 0; nti < 8; nti++) {
            int m = m0 + wm * 32 + mti * 16 + grp;
            int n = wn * 64 + nti * 8 + tig * 2;
            const float* cc = acc[mti][nti];
            attn[((size_t)(b * Sc + m) * HQc + h) * HDc + n]           = cc[0];
            attn[((size_t)(b * Sc + m) * HQc + h) * HDc + n + 1]       = cc[1];
            attn[((size_t)(b * Sc + m + 8) * HQc + h) * HDc + n]       = cc[2];
            attn[((size_t)(b * Sc + m + 8) * HQc + h) * HDc + n + 1]   = cc[3];
        }
}

// ---------------- elementwise silu(a)*b -> a ----------------
__global__ void __launch_bounds__(256) silumul_kernel(float* __restrict__ a,
                                                      const float* __restrict__ b,
                                                      int n) {
    int i = blockIdx.x * 256 + threadIdx.x;
    if (i < n) {
        float v = a[i];
        a[i] = v / (1.f + expf(-v)) * b[i];
    }
}

// ---------------- router: logits, sigmoid, top-4, renorm ----------------
__global__ void __launch_bounds__(256) router_kernel(const float* __restrict__ x,
                                                     const float* __restrict__ gate_w) {
    int t = blockIdx.x;
    int tid = threadIdx.x;
    int lane = tid & 31, w = tid >> 5;   // 8 warps x 4 experts each
    const float* xr = x + (size_t)t * Dc;
    float acc[4] = {0.f, 0.f, 0.f, 0.f};
    for (int d = lane; d < Dc; d += 32) {
        float xv = xr[d];
        #pragma unroll
        for (int j = 0; j < 4; j++)
            acc[j] = fmaf(xv, gate_w[(size_t)d * Ec + w * 4 + j], acc[j]);
    }
    #pragma unroll
    for (int j = 0; j < 4; j++)
        for (int o = 16; o > 0; o >>= 1)
            acc[j] += __shfl_down_sync(0xffffffffu, acc[j], o);
    __shared__ float lg[Ec];
    if (lane == 0) {
        #pragma unroll
        for (int j = 0; j < 4; j++) lg[w * 4 + j] = acc[j];
    }
    __syncthreads();
    if (tid == 0) {
        float gg[Ec];
        #pragma unroll
        for (int e = 0; e < Ec; e++) gg[e] = 1.f / (1.f + expf(-lg[e]));
        float tv[TOPK]; int ti[TOPK]; float sum = 0.f;
        for (int j = 0; j < TOPK; j++) {
            int best = 0; float bv = -1e30f;
            for (int e = 0; e < Ec; e++)
                if (gg[e] > bv) { bv = gg[e]; best = e; }
            gg[best] = -1e30f;
            tv[j] = bv; ti[j] = best; sum += bv;
        }
        float inv = 1.f / sum;
        for (int j = 0; j < TOPK; j++) {
            g_topi[t * TOPK + j] = ti[j];
            g_topw[t * TOPK + j] = tv[j] * inv;
        }
    }
}

// ---------------- expert grouping ----------------
__global__ void __launch_bounds__(256) count_scan_kernel() {
    __shared__ int sc[Ec];
    int tid = threadIdx.x;
    if (tid < Ec) sc[tid] = 0;
    __syncthreads();
    for (int i = tid; i < Tc * TOPK; i += 256) atomicAdd(&sc[g_topi[i]], 1);
    __syncthreads();
    if (tid == 0) {
        int run = 0;
        for (int e = 0; e < Ec; e++) {
            g_offsets[e] = run; g_cursor[e] = run; g_counts[e] = sc[e];
            run += sc[e];
        }
    }
}

__global__ void __launch_bounds__(256) scatter_kernel() {
    int i = blockIdx.x * 256 + threadIdx.x;
    if (i < Tc * TOPK) {
        int t = i >> 2;
        int e = g_topi[i];
        int p = atomicAdd(&g_cursor[e], 1);
        g_slot_tok[p] = t;
        g_slot_w[p] = g_topw[i];
    }
}

// ---------------- routed expert up/gate GEMM (tf32, gathered A rows) ----------------
__global__ void __launch_bounds__(256) moe_up_tf32_kernel(const float* __restrict__ X,
                                                          const float* __restrict__ W,
                                                          float* __restrict__ Cb,
                                                          int N, int Kd) {
    __shared__ uint32_t As[2][128][20];
    __shared__ uint32_t Bs[2][16][136];
    int e = blockIdx.z;
    int cnt = g_counts[e];
    int m0 = blockIdx.y * 128;
    if (m0 >= cnt) return;
    int off = g_offsets[e];
    int n0 = blockIdx.x * 128;
    TF_DECL;
    bool aValid = (m0 + aRow) < cnt;
    const float* Aptr = X;
    if (aValid) Aptr = X + (size_t)g_slot_tok[off + m0 + aRow] * Kd + aCol;
    const float* Bptr = W + (size_t)e * Kd * N + (size_t)bRow * N + n0 + bCol;

    const float4 z4 = make_float4(0.f, 0.f, 0.f, 0.f);
    float4 av0 = z4, av1 = z4;
    if (aValid) { av0 = *(const float4*)(Aptr); av1 = *(const float4*)(Aptr + 4); }
    float4 bv0 = *(const float4*)(Bptr);
    float4 bv1 = *(const float4*)(Bptr + 4);
    TF_STORE(0);
    __syncthreads();

    int nTiles = Kd >> 4;
    for (int t = 0; t < nTiles; t++) {
        int cur = t & 1, nxt = cur ^ 1;
        if (t + 1 < nTiles) {
            int k0 = (t + 1) << 4;
            av0 = z4; av1 = z4;
            if (aValid) {
                av0 = *(const float4*)(Aptr + k0);
                av1 = *(const float4*)(Aptr + k0 + 4);
            }
            bv0 = *(const float4*)(Bptr + (size_t)k0 * N);
            bv1 = *(const float4*)(Bptr + (size_t)k0 * N + 4);
        }
        if (cur == 0) { TF_COMPUTE(0); } else { TF_COMPUTE(1); }
        if (t + 1 < nTiles) {
            if (nxt == 0) { TF_STORE(0); } else { TF_STORE(1); }
        }
        __syncthreads();
    }
    #pragma unroll
    for (int mti = 0; mti < 2; mti++)
        #pragma unroll
        for (int nti = 0; nti < 8; nti++) {
            int r = m0 + wm * 32 + mti * 16 + grp;
            int n = n0 + wn * 64 + nti * 8 + tig * 2;
            const float* cc = acc[mti][nti];
            if (r < cnt) {
                Cb[(size_t)(off + r) * N + n]     = cc[0];
                Cb[(size_t)(off + r) * N + n + 1] = cc[1];
            }
            if (r + 8 < cnt) {
                Cb[(size_t)(off + r + 8) * N + n]     = cc[2];
                Cb[(size_t)(off + r + 8) * N + n + 1] = cc[3];
            }
        }
}

// ---------------- routed expert down GEMM (tf32): atomicAdd w*(inter @ wd) into out ----------------
__global__ void __launch_bounds__(256) moe_down_tf32_kernel(const float* __restrict__ Ibuf,
                                                            const float* __restrict__ Wd,
                                                            float* __restrict__ out,
                                                            int N, int Kd) {
    __shared__ uint32_t As[2][128][20];
    __shared__ uint32_t Bs[2][16][136];
    int e = blockIdx.z;
    int cnt = g_counts[e];
    int m0 = blockIdx.y * 128;
    if (m0 >= cnt) return;
    int off = g_offsets[e];
    int n0 = blockIdx.x * 128;
    TF_DECL;
    bool aValid = (m0 + aRow) < cnt;
    const float* Aptr = Ibuf + (size_t)(off + m0 + aRow) * Kd + aCol;
    const float* Bptr = Wd + (size_t)e * Kd * N + (size_t)bRow * N + n0 + bCol;

    const float4 z4 = make_float4(0.f, 0.f, 0.f, 0.f);
    float4 av0 = z4, av1 = z4;
    if (aValid) { av0 = *(const float4*)(Aptr); av1 = *(const float4*)(Aptr + 4); }
    float4 bv0 = *(const float4*)(Bptr);
    float4 bv1 = *(const float4*)(Bptr + 4);
    TF_STORE(0);
    __syncthreads();

    int nTiles = Kd >> 4;
    for (int t = 0; t < nTiles; t++) {
        int cur = t & 1, nxt = cur ^ 1;
        if (t + 1 < nTiles) {
            int k0 = (t + 1) << 4;
            av0 = z4; av1 = z4;
            if (aValid) {
                av0 = *(const float4*)(Aptr + k0);
                av1 = *(const float4*)(Aptr + k0 + 4);
            }
            bv0 = *(const float4*)(Bptr + (size_t)k0 * N);
            bv1 = *(const float4*)(Bptr + (size_t)k0 * N + 4);
        }
        if (cur == 0) { TF_COMPUTE(0); } else { TF_COMPUTE(1); }
        if (t + 1 < nTiles) {
            if (nxt == 0) { TF_STORE(0); } else { TF_STORE(1); }
        }
        __syncthreads();
    }
    #pragma unroll
    for (int mti = 0; mti < 2; mti++)
        #pragma unroll
        for (int nti = 0; nti < 8; nti++) {
            int r = m0 + wm * 32 + mti * 16 + grp;
            int n = n0 + wn * 64 + nti * 8 + tig * 2;
            const float* cc = acc[mti][nti];
            if (r < cnt) {
                int slot = off + r;
                int tok = g_slot_tok[slot];
                float wgt = g_slot_w[slot];
                atomicAdd(&out[(size_t)tok * N + n],     wgt * cc[0]);
                atomicAdd(&out[(size_t)tok * N + n + 1], wgt * cc[1]);
            }
            if (r + 8 < cnt) {
                int slot = off + r + 8;
                int tok = g_slot_tok[slot];
                float wgt = g_slot_w[slot];
                atomicAdd(&out[(size_t)tok * N + n],     wgt * cc[2]);
                atomicAdd(&out[(size_t)tok * N + n + 1], wgt * cc[3]);
            }
        }
}

// ---------------- combine: out = shared + resid2 (moe atomicAdded afterwards) ----------------
__global__ void __launch_bounds__(256) combine_kernel(float* __restrict__ out) {
    int i = blockIdx.x * 256 + threadIdx.x;
    if (i < Tc * Dc) out[i] = g_sh[i] + g_h2[i];
}

// ---------------- host launch ----------------
extern "C" void kernel_launch(void* const* d_in, const int* in_sizes, int n_in,
                              void* d_out, int out_size) {
    const int*   positions = (const int*)d_in[0];
    const float* hidden    = (const float*)d_in[1];
    const float* in_ln     = (const float*)d_in[2];
    const float* post_ln   = (const float*)d_in[3];
    const float* q_norm    = (const float*)d_in[4];
    const float* k_norm    = (const float*)d_in[5];
    const float* wq        = (const float*)d_in[6];
    const float* wk        = (const float*)d_in[7];
    const float* wv        = (const float*)d_in[8];
    const float* wo        = (const float*)d_in[9];
    const float* gate_w    = (const float*)d_in[10];
    const float* sh_wg     = (const float*)d_in[11];
    const float* sh_wu     = (const float*)d_in[12];
    const float* sh_wd     = (const float*)d_in[13];
    const float* e_wg      = (const float*)d_in[14];
    const float* e_wu      = (const float*)d_in[15];
    const float* e_wd      = (const float*)d_in[16];
    float* out = (float*)d_out;

    float *p_h, *p_q, *p_k, *p_v, *p_scores, *p_attn, *p_h2, *p_x, *p_g1, *p_u1,
          *p_sh, *p_eg, *p_eu;
    cudaGetSymbolAddress((void**)&p_h, g_h);
    cudaGetSymbolAddress((void**)&p_q, g_q);
    cudaGetSymbolAddress((void**)&p_k, g_k);
    cudaGetSymbolAddress((void**)&p_v, g_v);
    cudaGetSymbolAddress((void**)&p_scores, g_scores);
    cudaGetSymbolAddress((void**)&p_attn, g_attn);
    cudaGetSymbolAddress((void**)&p_h2, g_h2);
    cudaGetSymbolAddress((void**)&p_x, g_x);
    cudaGetSymbolAddress((void**)&p_g1, g_g1);
    cudaGetSymbolAddress((void**)&p_u1, g_u1);
    cudaGetSymbolAddress((void**)&p_sh, g_sh);
    cudaGetSymbolAddress((void**)&p_eg, g_eg);
    cudaGetSymbolAddress((void**)&p_eu, g_eu);

    // 1. input RMSNorm
    rmsnorm_kernel<<<Tc, 256>>>(hidden, in_ln, p_h);

    // 2-4. QKV projections (tf32)
    sgemm_tf32_kernel<<<dim3((HQc*HDc)/128, Tc/128), 256>>>(p_h, wq, p_q, nullptr,
        Tc, HQc*HDc, Dc, Dc, HQc*HDc, HQc*HDc);
    sgemm_tf32_kernel<<<dim3((HKVc*HDc)/128, Tc/128), 256>>>(p_h, wk, p_k, nullptr,
        Tc, HKVc*HDc, Dc, Dc, HKVc*HDc, HKVc*HDc);
    sgemm_tf32_kernel<<<dim3((HKVc*HDc)/128, Tc/128), 256>>>(p_h, wv, p_v, nullptr,
        Tc, HKVc*HDc, Dc, Dc, HKVc*HDc, HKVc*HDc);

    // 5. qk-norm + RoPE
    qknorm_rope_kernel<<<dim3(Tc, HQc), 128>>>(p_q, q_norm, positions, HQc);
    qknorm_rope_kernel<<<dim3(Tc, HKVc), 128>>>(p_k, k_norm, positions, HKVc);

    // 6. scores (fp32, causal tile skip)
    qk_score_kernel<<<dim3(Sc/64, Sc/64, Bc*HQc), 256>>>(p_q, p_k, p_scores);

    // 7. causal softmax (bounded zero-fill)
    softmax_kernel<<<dim3(Sc, Bc*HQc), 256>>>(p_scores);

    // 8. attn = P @ V (tf32)
    attnv_tf32_kernel<<<dim3(1, Sc/128, Bc*HQc), 256>>>(p_scores, p_v, p_attn);

    // 9. output proj + residual (tf32)
    sgemm_tf32_kernel<<<dim3(Dc/128, Tc/128), 256>>>(p_attn, wo, p_h2, hidden,
        Tc, Dc, HQc*HDc, HQc*HDc, Dc, Dc);

    // 10. post-attn RMSNorm
    rmsnorm_kernel<<<Tc, 256>>>(p_h2, post_ln, p_x);

    // 11-13. shared expert SwiGLU (tf32)
    sgemm_tf32_kernel<<<dim3(FSc/128, Tc/128), 256>>>(p_x, sh_wg, p_g1, nullptr,
        Tc, FSc, Dc, Dc, FSc, FSc);
    sgemm_tf32_kernel<<<dim3(FSc/128, Tc/128), 256>>>(p_x, sh_wu, p_u1, nullptr,
        Tc, FSc, Dc, Dc, FSc, FSc);
    silumul_kernel<<<(Tc*FSc + 255)/256, 256>>>(p_g1, p_u1, Tc*FSc);
    sgemm_tf32_kernel<<<dim3(Dc/128, Tc/128), 256>>>(p_g1, sh_wd, p_sh, nullptr,
        Tc, Dc, FSc, FSc, Dc, Dc);

    // 14-16. routing + grouping
    router_kernel<<<Tc, 256>>>(p_x, gate_w);
    count_scan_kernel<<<1, 256>>>();
    scatter_kernel<<<(Tc*TOPK + 255)/256, 256>>>();

    // 17-18. routed experts (tf32): gate/up (gathered), silu-mul
    moe_up_tf32_kernel<<<dim3(Fc/128, (Tc*TOPK)/128, Ec), 256>>>(p_x, e_wg, p_eg, Fc, Dc);
    moe_up_tf32_kernel<<<dim3(Fc/128, (Tc*TOPK)/128, Ec), 256>>>(p_x, e_wu, p_eu, Fc, Dc);
    silumul_kernel<<<(Tc*TOPK*Fc + 255)/256, 256>>>(p_eg, p_eu, Tc*TOPK*Fc);

    // 19. init out = shared + resid2 (must precede down-proj atomics)
    combine_kernel<<<(Tc*Dc + 255)/256, 256>>>(out);

    // 20. routed down-proj (tf32), weighted atomic accumulate into out
    moe_down_tf32_kernel<<<dim3(Dc/128, (Tc*TOPK)/128, Ec), 256>>>(p_eg, e_wd, out, Dc, Fc);
}